// round 1
// baseline (speedup 1.0000x reference)
#include <cuda_runtime.h>
#include <math.h>

// ---------------------------------------------------------------------------
// GridFeatureToPointGraphConv
//   grid: regular 48^3 over [-1,1], SCALER = 24
//   per point: 16-NN among grid vertices (provably inside 4x4x4 index window),
//   edge MLP (67->64->32, gelu-tanh), mean over K=16, out MLP 32->32 gelu.
//
//   Layer-1 factorization: e@W1 = GF@W1a (per-vertex, precomputed)
//                                + PF@W1b (per-point) + rel@W1c + b1
// ---------------------------------------------------------------------------

#define RES 48
#define NGRID (RES*RES*RES)      // 110592
#define NPTS 65536
#define HID 64
#define KNN 16

__device__ float g_Gpre[NGRID * HID];   // 28.3 MB scratch (fits in L2)

__device__ __forceinline__ float gelu_tanh(float x) {
    // jax.nn.gelu default (approximate=True): 0.5*x*(1+tanh(sqrt(2/pi)*(x+0.044715*x^3)))
    float x3 = x * x * x;
    return 0.5f * x * (1.0f + tanhf(0.7978845608028654f * (x + 0.044715f * x3)));
}

// ---------------------------------------------------------------------------
// Kernel 1: Gpre[g][i] = sum_c grid_features[g][c] * W1[c][i]   (rows 0..31)
// ---------------------------------------------------------------------------
__global__ __launch_bounds__(256) void gpre_kernel(const float* __restrict__ gf,
                                                   const float* __restrict__ W1) {
    __shared__ float W1s[32 * 64];
    __shared__ float gfs[4 * 32];
    int tid = threadIdx.x;
    for (int t = tid; t < 32 * 64; t += 256) W1s[t] = W1[t];

    int i = tid & 63;
    int v = tid >> 6;               // 0..3
    int base = blockIdx.x * 32;     // 32 vertices per block

    for (int it = 0; it < 8; ++it) {
        int g = base + it * 4;
        __syncthreads();
        if (tid < 128) gfs[tid] = gf[(size_t)g * 32 + tid];
        __syncthreads();
        float acc = 0.0f;
        #pragma unroll
        for (int c = 0; c < 32; ++c)
            acc = fmaf(gfs[v * 32 + c], W1s[c * 64 + i], acc);
        g_Gpre[(size_t)g * 64 + (size_t)tid] = acc;   // (g+v)*64 + i == g*64 + tid
    }
}

// ---------------------------------------------------------------------------
// Candidate distance, matching reference expansion: qq - 2*(q.p) + pp
// ---------------------------------------------------------------------------
__device__ __forceinline__ void cand_dist(int t, int ix0, int iy0, int iz0,
                                          const float* __restrict__ lins,
                                          float qx, float qy, float qz, float qq,
                                          float& d, int& g) {
    int a = t >> 4, b = (t >> 2) & 3, c = t & 3;
    int ix = ix0 + a, iy = iy0 + b, iz = iz0 + c;
    float px = lins[ix], py = lins[iy], pz = lins[iz];
    float pp = __fadd_rn(__fadd_rn(__fmul_rn(px, px), __fmul_rn(py, py)), __fmul_rn(pz, pz));
    float dot = __fmaf_rn(qz, pz, __fmaf_rn(qy, py, __fmul_rn(qx, px)));
    d = __fadd_rn(__fsub_rn(qq, __fadd_rn(dot, dot)), pp);  // qq - 2*dot + pp
    g = ix * (RES * RES) + iy * RES + iz;
}

// ---------------------------------------------------------------------------
// Kernel 2: fused KNN + edge MLP + mean + out MLP. One warp per point.
// ---------------------------------------------------------------------------
__global__ __launch_bounds__(256, 2) void fused_kernel(
    const float* __restrict__ gv,
    const float* __restrict__ pv,
    const float* __restrict__ pf,
    const float* __restrict__ W1,
    const float* __restrict__ b1,
    const float* __restrict__ W2,
    const float* __restrict__ b2,
    const float* __restrict__ W3,
    const float* __restrict__ b3,
    float* __restrict__ out)
{
    __shared__ float lins[RES];
    __shared__ float W1s[35 * 64];          // W1 rows 32..66 (self + rel)
    __shared__ float b1s[64];
    __shared__ float b2s[32];
    __shared__ float W3s[32 * 32];
    __shared__ float b3s[32];
    __shared__ __align__(16) float h1s[8][64];
    __shared__ float aggs[8][32];

    int tid = threadIdx.x;
    for (int t = tid; t < 35 * 64; t += 256) W1s[t] = W1[32 * 64 + t];
    for (int t = tid; t < 32 * 32; t += 256) W3s[t] = W3[t];
    if (tid < 64) b1s[tid] = b1[tid];
    if (tid >= 64 && tid < 96)  b2s[tid - 64] = b2[tid - 64];
    if (tid >= 96 && tid < 128) b3s[tid - 96] = b3[tid - 96];
    if (tid >= 128 && tid < 128 + RES)
        lins[tid - 128] = __fmul_rn(gv[3 * (tid - 128) + 2], 24.0f); // scaled linspace
    __syncthreads();

    const int w = tid >> 5;
    const int lane = tid & 31;
    const int p = blockIdx.x * 8 + w;

    // W2 column for this lane in registers (W2 is 64x32 row-major)
    float w2r[64];
    #pragma unroll
    for (int i2 = 0; i2 < 64; ++i2) w2r[i2] = __ldg(&W2[i2 * 32 + lane]);

    // point coordinates (scaled, matching out_v = point_vertices * 24)
    float qxu = __ldg(&pv[p * 3 + 0]);
    float qyu = __ldg(&pv[p * 3 + 1]);
    float qzu = __ldg(&pv[p * 3 + 2]);
    float qx = __fmul_rn(qxu, 24.0f);
    float qy = __fmul_rn(qyu, 24.0f);
    float qz = __fmul_rn(qzu, 24.0f);
    float qq = __fadd_rn(__fadd_rn(__fmul_rn(qx, qx), __fmul_rn(qy, qy)), __fmul_rn(qz, qz));

    // per-point layer-1 partial: b1 + point_features @ W1[32:64]
    float pre0 = b1s[lane];
    float pre1 = b1s[lane + 32];
    #pragma unroll
    for (int c = 0; c < 32; ++c) {
        float f = __ldg(&pf[(size_t)p * 32 + c]);
        pre0 = fmaf(f, W1s[c * 64 + lane], pre0);
        pre1 = fmaf(f, W1s[c * 64 + lane + 32], pre1);
    }

    // 4x4x4 candidate window (4 nearest indices per axis, clamped)
    int ix0 = min(max((int)floorf((qxu + 1.0f) * 23.5f) - 1, 0), RES - 4);
    int iy0 = min(max((int)floorf((qyu + 1.0f) * 23.5f) - 1, 0), RES - 4);
    int iz0 = min(max((int)floorf((qzu + 1.0f) * 23.5f) - 1, 0), RES - 4);

    float d0, d1; int g0, g1;
    cand_dist(lane,      ix0, iy0, iz0, lins, qx, qy, qz, qq, d0, g0);
    cand_dist(lane + 32, ix0, iy0, iz0, lins, qx, qy, qz, qq, d1, g1);

    float agg = 0.0f;

    #pragma unroll 1
    for (int k = 0; k < KNN; ++k) {
        // ---- select k-th nearest (min d, tie -> min index, = top_k order) ----
        float dm; int gm;
        if (d1 < d0 || (d1 == d0 && g1 < g0)) { dm = d1; gm = g1; }
        else                                  { dm = d0; gm = g0; }
        #pragma unroll
        for (int off = 16; off > 0; off >>= 1) {
            float od = __shfl_xor_sync(0xffffffffu, dm, off);
            int   og = __shfl_xor_sync(0xffffffffu, gm, off);
            if (od < dm || (od == dm && og < gm)) { dm = od; gm = og; }
        }
        if (g0 == gm) d0 = __int_as_float(0x7f800000);
        if (g1 == gm) d1 = __int_as_float(0x7f800000);

        // ---- edge MLP layer 1 ----
        int ix = gm / (RES * RES);
        int rem = gm - ix * (RES * RES);
        int iy = rem / RES;
        int iz = rem - iy * RES;
        float rx = __fsub_rn(lins[ix], qx);
        float ry = __fsub_rn(lins[iy], qy);
        float rz = __fsub_rn(lins[iz], qz);

        const float* gp = g_Gpre + (size_t)gm * 64;
        float t0 = __fadd_rn(pre0, __ldg(gp + lane));
        t0 = fmaf(rx, W1s[32 * 64 + lane], t0);
        t0 = fmaf(ry, W1s[33 * 64 + lane], t0);
        t0 = fmaf(rz, W1s[34 * 64 + lane], t0);
        float t1 = __fadd_rn(pre1, __ldg(gp + lane + 32));
        t1 = fmaf(rx, W1s[32 * 64 + lane + 32], t1);
        t1 = fmaf(ry, W1s[33 * 64 + lane + 32], t1);
        t1 = fmaf(rz, W1s[34 * 64 + lane + 32], t1);

        h1s[w][lane]      = gelu_tanh(t0);
        h1s[w][lane + 32] = gelu_tanh(t1);
        __syncwarp();

        // ---- edge MLP layer 2: h2[lane] = gelu(sum_i h1[i]*W2[i][lane] + b2) ----
        float acc = 0.0f;
        #pragma unroll
        for (int i2 = 0; i2 < 64; i2 += 4) {
            float4 h = *reinterpret_cast<const float4*>(&h1s[w][i2]);
            acc = fmaf(h.x, w2r[i2 + 0], acc);
            acc = fmaf(h.y, w2r[i2 + 1], acc);
            acc = fmaf(h.z, w2r[i2 + 2], acc);
            acc = fmaf(h.w, w2r[i2 + 3], acc);
        }
        agg = __fadd_rn(agg, gelu_tanh(__fadd_rn(acc, b2s[lane])));
        __syncwarp();
    }

    // ---- mean over K, out transform ----
    aggs[w][lane] = __fmul_rn(agg, 0.0625f);
    __syncwarp();
    float acc = 0.0f;
    #pragma unroll
    for (int i2 = 0; i2 < 32; ++i2)
        acc = fmaf(aggs[w][i2], W3s[i2 * 32 + lane], acc);
    out[(size_t)p * 32 + lane] = gelu_tanh(__fadd_rn(acc, b3s[lane]));
}

// ---------------------------------------------------------------------------
// launch
// ---------------------------------------------------------------------------
extern "C" void kernel_launch(void* const* d_in, const int* in_sizes, int n_in,
                              void* d_out, int out_size) {
    const float* gv = (const float*)d_in[0];   // grid_vertices   (110592,3)
    const float* gf = (const float*)d_in[1];   // grid_features   (110592,32)
    const float* pv = (const float*)d_in[2];   // point_vertices  (65536,3)
    const float* pf = (const float*)d_in[3];   // point_features  (65536,32)
    const float* W1 = (const float*)d_in[4];   // (67,64)
    const float* b1 = (const float*)d_in[5];   // (64,)
    const float* W2 = (const float*)d_in[6];   // (64,32)
    const float* b2 = (const float*)d_in[7];   // (32,)
    const float* W3 = (const float*)d_in[8];   // (32,32)
    const float* b3 = (const float*)d_in[9];   // (32,)
    float* out = (float*)d_out;                // (65536,32) f32

    gpre_kernel<<<NGRID / 32, 256>>>(gf, W1);
    fused_kernel<<<NPTS / 8, 256>>>(gv, pv, pf, W1, b1, W2, b2, W3, b3, out);
}

// round 2
// speedup vs baseline: 1.0508x; 1.0508x over previous
#include <cuda_runtime.h>
#include <math.h>

// ---------------------------------------------------------------------------
// GridFeatureToPointGraphConv — R2: phase-split (select / layer1 / layer2),
// float2 Gpre gathers, shfl-held neighbor list, k-unrolled layer-2.
// Numerics identical to R1 (tanhf gelu, same fp expression order).
// ---------------------------------------------------------------------------

#define RES 48
#define NGRID (RES*RES*RES)      // 110592
#define NPTS 65536
#define HID 64
#define KNN 16

__device__ float g_Gpre[NGRID * HID];   // 28.3 MB scratch (fits in L2)

__device__ __forceinline__ float gelu_tanh(float x) {
    float x3 = x * x * x;
    return 0.5f * x * (1.0f + tanhf(0.7978845608028654f * (x + 0.044715f * x3)));
}

// ---------------------------------------------------------------------------
// Kernel 1: Gpre[g][i] = sum_c grid_features[g][c] * W1[c][i]   (rows 0..31)
// ---------------------------------------------------------------------------
__global__ __launch_bounds__(256) void gpre_kernel(const float* __restrict__ gf,
                                                   const float* __restrict__ W1) {
    __shared__ float W1s[32 * 64];
    __shared__ float gfs[4 * 32];
    int tid = threadIdx.x;
    for (int t = tid; t < 32 * 64; t += 256) W1s[t] = W1[t];

    int i = tid & 63;
    int v = tid >> 6;
    int base = blockIdx.x * 32;

    for (int it = 0; it < 8; ++it) {
        int g = base + it * 4;
        __syncthreads();
        if (tid < 128) gfs[tid] = gf[(size_t)g * 32 + tid];
        __syncthreads();
        float acc = 0.0f;
        #pragma unroll
        for (int c = 0; c < 32; ++c)
            acc = fmaf(gfs[v * 32 + c], W1s[c * 64 + i], acc);
        g_Gpre[(size_t)g * 64 + (size_t)tid] = acc;
    }
}

// ---------------------------------------------------------------------------
// Candidate distance, matching reference expansion: qq - 2*(q.p) + pp
// ---------------------------------------------------------------------------
__device__ __forceinline__ void cand_dist(int t, int ix0, int iy0, int iz0,
                                          const float* __restrict__ lins,
                                          float qx, float qy, float qz, float qq,
                                          float& d, int& g) {
    int a = t >> 4, b = (t >> 2) & 3, c = t & 3;
    int ix = ix0 + a, iy = iy0 + b, iz = iz0 + c;
    float px = lins[ix], py = lins[iy], pz = lins[iz];
    float pp = __fadd_rn(__fadd_rn(__fmul_rn(px, px), __fmul_rn(py, py)), __fmul_rn(pz, pz));
    float dot = __fmaf_rn(qz, pz, __fmaf_rn(qy, py, __fmul_rn(qx, px)));
    d = __fadd_rn(__fsub_rn(qq, __fadd_rn(dot, dot)), pp);
    g = ix * (RES * RES) + iy * RES + iz;
}

// ---------------------------------------------------------------------------
// Kernel 2: fused KNN + edge MLP + mean + out MLP. One warp per point.
// ---------------------------------------------------------------------------
__global__ __launch_bounds__(256, 2) void fused_kernel(
    const float* __restrict__ gv,
    const float* __restrict__ pv,
    const float* __restrict__ pf,
    const float* __restrict__ W1,
    const float* __restrict__ b1,
    const float* __restrict__ W2,
    const float* __restrict__ b2,
    const float* __restrict__ W3,
    const float* __restrict__ b3,
    float* __restrict__ out)
{
    __shared__ float lins[RES];
    __shared__ float W1s[35 * 64];          // W1 rows 32..66 (self + rel)
    __shared__ float b1s[64];
    __shared__ float b2s[32];
    __shared__ float W3s[32 * 32];
    __shared__ float b3s[32];
    __shared__ __align__(16) float h1s[8][16][64];   // per-warp, per-edge hidden
    __shared__ float aggs[8][32];

    int tid = threadIdx.x;
    for (int t = tid; t < 35 * 64; t += 256) W1s[t] = W1[32 * 64 + t];
    for (int t = tid; t < 32 * 32; t += 256) W3s[t] = W3[t];
    if (tid < 64) b1s[tid] = b1[tid];
    if (tid >= 64 && tid < 96)  b2s[tid - 64] = b2[tid - 64];
    if (tid >= 96 && tid < 128) b3s[tid - 96] = b3[tid - 96];
    if (tid >= 128 && tid < 128 + RES)
        lins[tid - 128] = __fmul_rn(gv[3 * (tid - 128) + 2], 24.0f);
    __syncthreads();

    const int w = tid >> 5;
    const int lane = tid & 31;
    const int p = blockIdx.x * 8 + w;
    const int c0 = lane * 2;                // this lane owns hidden channels c0, c0+1

    // W2 column for this lane (output channel = lane), W2 is 64x32 row-major
    float w2r[64];
    #pragma unroll
    for (int i2 = 0; i2 < 64; ++i2) w2r[i2] = __ldg(&W2[i2 * 32 + lane]);

    // point coords (scaled)
    float qxu = __ldg(&pv[p * 3 + 0]);
    float qyu = __ldg(&pv[p * 3 + 1]);
    float qzu = __ldg(&pv[p * 3 + 2]);
    float qx = __fmul_rn(qxu, 24.0f);
    float qy = __fmul_rn(qyu, 24.0f);
    float qz = __fmul_rn(qzu, 24.0f);
    float qq = __fadd_rn(__fadd_rn(__fmul_rn(qx, qx), __fmul_rn(qy, qy)), __fmul_rn(qz, qz));

    // per-point layer-1 partial for channels c0,c0+1: b1 + pf @ W1[32:64]
    const float2* W1s2 = reinterpret_cast<const float2*>(W1s);
    float pre0 = b1s[c0];
    float pre1 = b1s[c0 + 1];
    #pragma unroll
    for (int c = 0; c < 32; ++c) {
        float f = __ldg(&pf[(size_t)p * 32 + c]);
        float2 wv = W1s2[c * 32 + lane];
        pre0 = fmaf(f, wv.x, pre0);
        pre1 = fmaf(f, wv.y, pre1);
    }
    // rel-pos rows of W1 (rows 32,33,34 of W1s) for channels c0,c0+1 (loop-invariant)
    float2 w1rx = W1s2[32 * 32 + lane];
    float2 w1ry = W1s2[33 * 32 + lane];
    float2 w1rz = W1s2[34 * 32 + lane];

    // ---- Phase A: selection (4x4x4 window, extract 16 nearest in order) ----
    int ix0 = min(max((int)floorf((qxu + 1.0f) * 23.5f) - 1, 0), RES - 4);
    int iy0 = min(max((int)floorf((qyu + 1.0f) * 23.5f) - 1, 0), RES - 4);
    int iz0 = min(max((int)floorf((qzu + 1.0f) * 23.5f) - 1, 0), RES - 4);

    float d0, d1; int g0, g1;
    cand_dist(lane,      ix0, iy0, iz0, lins, qx, qy, qz, qq, d0, g0);
    cand_dist(lane + 32, ix0, iy0, iz0, lins, qx, qy, qz, qq, d1, g1);

    int myg = 0;                             // lane k (<16) keeps k-th neighbor
    #pragma unroll 1
    for (int k = 0; k < KNN; ++k) {
        float dm; int gm;
        if (d1 < d0 || (d1 == d0 && g1 < g0)) { dm = d1; gm = g1; }
        else                                  { dm = d0; gm = g0; }
        #pragma unroll
        for (int off = 16; off > 0; off >>= 1) {
            float od = __shfl_xor_sync(0xffffffffu, dm, off);
            int   og = __shfl_xor_sync(0xffffffffu, gm, off);
            if (od < dm || (od == dm && og < gm)) { dm = od; gm = og; }
        }
        if (g0 == gm) d0 = __int_as_float(0x7f800000);
        if (g1 == gm) d1 = __int_as_float(0x7f800000);
        if (lane == k) myg = gm;
    }

    // ---- Phase B1: edge layer-1 for all 16 edges (independent iterations) ----
    const float2* Gpre2 = reinterpret_cast<const float2*>(g_Gpre);
    float2* h1w2 = reinterpret_cast<float2*>(&h1s[w][0][0]);
    #pragma unroll 4
    for (int k = 0; k < KNN; ++k) {
        int gm = __shfl_sync(0xffffffffu, myg, k);
        int ix = gm / (RES * RES);
        int rem = gm - ix * (RES * RES);
        int iy = rem / RES;
        int iz = rem - iy * RES;
        float rx = __fsub_rn(lins[ix], qx);
        float ry = __fsub_rn(lins[iy], qy);
        float rz = __fsub_rn(lins[iz], qz);

        float2 gp = __ldg(&Gpre2[(size_t)gm * 32 + lane]);
        float t0 = __fadd_rn(pre0, gp.x);
        t0 = fmaf(rx, w1rx.x, t0);
        t0 = fmaf(ry, w1ry.x, t0);
        t0 = fmaf(rz, w1rz.x, t0);
        float t1 = __fadd_rn(pre1, gp.y);
        t1 = fmaf(rx, w1rx.y, t1);
        t1 = fmaf(ry, w1ry.y, t1);
        t1 = fmaf(rz, w1rz.y, t1);

        float2 hv;
        hv.x = gelu_tanh(t0);
        hv.y = gelu_tanh(t1);
        h1w2[k * 32 + lane] = hv;
    }
    __syncwarp();

    // ---- Phase B2: layer-2 + gelu + accumulate (dot order identical to R1) ----
    float b2v = b2s[lane];
    float agg = 0.0f;
    #pragma unroll 2
    for (int k = 0; k < KNN; ++k) {
        const float* hk = &h1s[w][k][0];
        float acc = 0.0f;
        #pragma unroll
        for (int i2 = 0; i2 < 64; i2 += 4) {
            float4 h = *reinterpret_cast<const float4*>(hk + i2);
            acc = fmaf(h.x, w2r[i2 + 0], acc);
            acc = fmaf(h.y, w2r[i2 + 1], acc);
            acc = fmaf(h.z, w2r[i2 + 2], acc);
            acc = fmaf(h.w, w2r[i2 + 3], acc);
        }
        agg = __fadd_rn(agg, gelu_tanh(__fadd_rn(acc, b2v)));
    }

    // ---- mean over K, out transform ----
    aggs[w][lane] = __fmul_rn(agg, 0.0625f);
    __syncwarp();
    float acc = 0.0f;
    #pragma unroll
    for (int i2 = 0; i2 < 32; ++i2)
        acc = fmaf(aggs[w][i2], W3s[i2 * 32 + lane], acc);
    out[(size_t)p * 32 + lane] = gelu_tanh(__fadd_rn(acc, b3s[lane]));
}

// ---------------------------------------------------------------------------
// launch
// ---------------------------------------------------------------------------
extern "C" void kernel_launch(void* const* d_in, const int* in_sizes, int n_in,
                              void* d_out, int out_size) {
    const float* gv = (const float*)d_in[0];
    const float* gf = (const float*)d_in[1];
    const float* pv = (const float*)d_in[2];
    const float* pf = (const float*)d_in[3];
    const float* W1 = (const float*)d_in[4];
    const float* b1 = (const float*)d_in[5];
    const float* W2 = (const float*)d_in[6];
    const float* b2 = (const float*)d_in[7];
    const float* W3 = (const float*)d_in[8];
    const float* b3 = (const float*)d_in[9];
    float* out = (float*)d_out;

    gpre_kernel<<<NGRID / 32, 256>>>(gf, W1);
    fused_kernel<<<NPTS / 8, 256>>>(gv, pv, pf, W1, b1, W2, b2, W3, b3, out);
}

// round 3
// speedup vs baseline: 1.2865x; 1.2242x over previous
#include <cuda_runtime.h>
#include <math.h>

// ---------------------------------------------------------------------------
// GridFeatureToPointGraphConv — R3: fast sigmoid-form gelu (MUFU.EX2/RCP),
// bitonic-sort KNN selection (u64 keys, exact fp order + index tie-break),
// float4 point-feature loads. Selection set & sum orders identical to R2.
// ---------------------------------------------------------------------------

#define RES 48
#define NGRID (RES*RES*RES)      // 110592
#define NPTS 65536
#define HID 64
#define KNN 16

typedef unsigned long long u64;

__device__ float g_Gpre[NGRID * HID];   // 28.3 MB scratch (fits in L2)

// gelu_tanh(x) = 0.5x(1+tanh(0.79788456(x+0.044715x^3))) == x / (1 + e^{-p}),
// p = 1.5957691216x + 0.07135481681x^3
__device__ __forceinline__ float gelu_fast(float x) {
    float u = x * x;
    float w = __fmaf_rn(0.07135481681f, u, 1.5957691216f);
    float p = x * w;
    float e = __expf(-p);
    return __fdividef(x, 1.0f + e);
}

// ---------------------------------------------------------------------------
// Kernel 1: Gpre[g][i] = sum_c grid_features[g][c] * W1[c][i]   (rows 0..31)
// ---------------------------------------------------------------------------
__global__ __launch_bounds__(256) void gpre_kernel(const float* __restrict__ gf,
                                                   const float* __restrict__ W1) {
    __shared__ float W1s[32 * 64];
    __shared__ float gfs[4 * 32];
    int tid = threadIdx.x;
    for (int t = tid; t < 32 * 64; t += 256) W1s[t] = W1[t];

    int i = tid & 63;
    int v = tid >> 6;
    int base = blockIdx.x * 32;

    for (int it = 0; it < 8; ++it) {
        int g = base + it * 4;
        __syncthreads();
        if (tid < 128) gfs[tid] = gf[(size_t)g * 32 + tid];
        __syncthreads();
        float acc = 0.0f;
        #pragma unroll
        for (int c = 0; c < 32; ++c)
            acc = fmaf(gfs[v * 32 + c], W1s[c * 64 + i], acc);
        g_Gpre[(size_t)g * 64 + (size_t)tid] = acc;
    }
}

// ---------------------------------------------------------------------------
// Candidate distance, matching reference expansion: qq - 2*(q.p) + pp
// ---------------------------------------------------------------------------
__device__ __forceinline__ float cand_dist(int t, int ix0, int iy0, int iz0,
                                           const float* __restrict__ lins,
                                           float qx, float qy, float qz, float qq) {
    int a = t >> 4, b = (t >> 2) & 3, c = t & 3;
    float px = lins[ix0 + a], py = lins[iy0 + b], pz = lins[iz0 + c];
    float pp = __fadd_rn(__fadd_rn(__fmul_rn(px, px), __fmul_rn(py, py)), __fmul_rn(pz, pz));
    float dot = __fmaf_rn(qz, pz, __fmaf_rn(qy, py, __fmul_rn(qx, px)));
    return __fadd_rn(__fsub_rn(qq, __fadd_rn(dot, dot)), pp);
}

// monotone map: float -> u32 preserving < order (handles tiny negatives)
__device__ __forceinline__ unsigned int fmap(float d) {
    unsigned int b = __float_as_uint(d);
    return (b & 0x80000000u) ? ~b : (b | 0x80000000u);
}

// bitonic compare-exchange across lanes at distance j; up = ascending block
__device__ __forceinline__ u64 bitonic_ce(u64 key, int j, bool up, int lane) {
    u64 pk = __shfl_xor_sync(0xffffffffu, key, j);
    bool lower = ((lane & j) == 0);
    u64 mn = (key < pk) ? key : pk;
    u64 mx = (key < pk) ? pk : key;
    return ((lower == up)) ? mn : mx;
}

// ---------------------------------------------------------------------------
// Kernel 2: fused KNN + edge MLP + mean + out MLP. One warp per point.
// ---------------------------------------------------------------------------
__global__ __launch_bounds__(256, 2) void fused_kernel(
    const float* __restrict__ gv,
    const float* __restrict__ pv,
    const float* __restrict__ pf,
    const float* __restrict__ W1,
    const float* __restrict__ b1,
    const float* __restrict__ W2,
    const float* __restrict__ b2,
    const float* __restrict__ W3,
    const float* __restrict__ b3,
    float* __restrict__ out)
{
    __shared__ float lins[RES];
    __shared__ float W1s[35 * 64];          // W1 rows 32..66 (self + rel)
    __shared__ float b1s[64];
    __shared__ float b2s[32];
    __shared__ float W3s[32 * 32];
    __shared__ float b3s[32];
    __shared__ __align__(16) float h1s[8][16][64];   // per-warp, per-edge hidden
    __shared__ float aggs[8][32];

    int tid = threadIdx.x;
    for (int t = tid; t < 35 * 64; t += 256) W1s[t] = W1[32 * 64 + t];
    for (int t = tid; t < 32 * 32; t += 256) W3s[t] = W3[t];
    if (tid < 64) b1s[tid] = b1[tid];
    if (tid >= 64 && tid < 96)  b2s[tid - 64] = b2[tid - 64];
    if (tid >= 96 && tid < 128) b3s[tid - 96] = b3[tid - 96];
    if (tid >= 128 && tid < 128 + RES)
        lins[tid - 128] = __fmul_rn(gv[3 * (tid - 128) + 2], 24.0f);
    __syncthreads();

    const int w = tid >> 5;
    const int lane = tid & 31;
    const int p = blockIdx.x * 8 + w;

    // W2 column for this lane (output channel = lane), W2 is 64x32 row-major
    float w2r[64];
    #pragma unroll
    for (int i2 = 0; i2 < 64; ++i2) w2r[i2] = __ldg(&W2[i2 * 32 + lane]);

    // point coords (scaled)
    float qxu = __ldg(&pv[p * 3 + 0]);
    float qyu = __ldg(&pv[p * 3 + 1]);
    float qzu = __ldg(&pv[p * 3 + 2]);
    float qx = __fmul_rn(qxu, 24.0f);
    float qy = __fmul_rn(qyu, 24.0f);
    float qz = __fmul_rn(qzu, 24.0f);
    float qq = __fadd_rn(__fadd_rn(__fmul_rn(qx, qx), __fmul_rn(qy, qy)), __fmul_rn(qz, qz));

    // per-point layer-1 partial for channels 2*lane, 2*lane+1 (float4 pf loads)
    const float2* W1s2 = reinterpret_cast<const float2*>(W1s);
    float pre0 = b1s[lane * 2];
    float pre1 = b1s[lane * 2 + 1];
    {
        const float4* pf4 = reinterpret_cast<const float4*>(pf + (size_t)p * 32);
        #pragma unroll
        for (int c4 = 0; c4 < 8; ++c4) {
            float4 f = __ldg(&pf4[c4]);
            float2 wv;
            wv = W1s2[(c4 * 4 + 0) * 32 + lane]; pre0 = fmaf(f.x, wv.x, pre0); pre1 = fmaf(f.x, wv.y, pre1);
            wv = W1s2[(c4 * 4 + 1) * 32 + lane]; pre0 = fmaf(f.y, wv.x, pre0); pre1 = fmaf(f.y, wv.y, pre1);
            wv = W1s2[(c4 * 4 + 2) * 32 + lane]; pre0 = fmaf(f.z, wv.x, pre0); pre1 = fmaf(f.z, wv.y, pre1);
            wv = W1s2[(c4 * 4 + 3) * 32 + lane]; pre0 = fmaf(f.w, wv.x, pre0); pre1 = fmaf(f.w, wv.y, pre1);
        }
    }
    float2 w1rx = W1s2[32 * 32 + lane];
    float2 w1ry = W1s2[33 * 32 + lane];
    float2 w1rz = W1s2[34 * 32 + lane];

    // ---- Phase A: selection via bitonic sort of 64 (d, t) keys ----
    int ix0 = min(max((int)floorf((qxu + 1.0f) * 23.5f) - 1, 0), RES - 4);
    int iy0 = min(max((int)floorf((qyu + 1.0f) * 23.5f) - 1, 0), RES - 4);
    int iz0 = min(max((int)floorf((qzu + 1.0f) * 23.5f) - 1, 0), RES - 4);

    // element e = slot*32 + lane; candidate t = e. key = fmap(d)<<32 | t
    // (within window, ordering by t == ordering by global index: exact tie-break)
    float dA = cand_dist(lane,      ix0, iy0, iz0, lins, qx, qy, qz, qq);
    float dB = cand_dist(lane + 32, ix0, iy0, iz0, lins, qx, qy, qz, qq);
    u64 key0 = ((u64)fmap(dA) << 32) | (unsigned int)lane;
    u64 key1 = ((u64)fmap(dB) << 32) | (unsigned int)(lane + 32);

    // stages k=2..32 (cross-lane CEs only; slots are independent blocks)
    #pragma unroll
    for (int ks = 2; ks <= 32; ks <<= 1) {
        bool up0 = ((lane & ks) == 0);           // e0 = lane
        bool up1 = (((lane + 32) & ks) == 0);    // e1 = lane + 32
        #pragma unroll
        for (int j = ks >> 1; j > 0; j >>= 1) {
            key0 = bitonic_ce(key0, j, up0, lane);
            key1 = bitonic_ce(key1, j, up1, lane);
        }
    }
    // final stage k=64: j=32 is the slot swap (all ascending), then j=16..1
    {
        u64 mn = (key0 < key1) ? key0 : key1;
        u64 mx = (key0 < key1) ? key1 : key0;
        key0 = mn; key1 = mx;
        #pragma unroll
        for (int j = 16; j > 0; j >>= 1) {
            key0 = bitonic_ce(key0, j, true, lane);
            key1 = bitonic_ce(key1, j, true, lane);
        }
    }
    int myt = (int)((unsigned int)key0 & 63u);   // lane k (<16) holds rank-k neighbor

    // ---- Phase B1: edge layer-1 for all 16 edges ----
    const float2* Gpre2 = reinterpret_cast<const float2*>(g_Gpre);
    float2* h1w2 = reinterpret_cast<float2*>(&h1s[w][0][0]);
    const int gbase = ix0 * (RES * RES) + iy0 * RES + iz0;
    #pragma unroll 4
    for (int k = 0; k < KNN; ++k) {
        int t = __shfl_sync(0xffffffffu, myt, k);
        int a = t >> 4, b = (t >> 2) & 3, c = t & 3;
        int gm = gbase + a * (RES * RES) + b * RES + c;
        float rx = __fsub_rn(lins[ix0 + a], qx);
        float ry = __fsub_rn(lins[iy0 + b], qy);
        float rz = __fsub_rn(lins[iz0 + c], qz);

        float2 gp = __ldg(&Gpre2[(size_t)gm * 32 + lane]);
        float t0 = __fadd_rn(pre0, gp.x);
        t0 = fmaf(rx, w1rx.x, t0);
        t0 = fmaf(ry, w1ry.x, t0);
        t0 = fmaf(rz, w1rz.x, t0);
        float t1 = __fadd_rn(pre1, gp.y);
        t1 = fmaf(rx, w1rx.y, t1);
        t1 = fmaf(ry, w1ry.y, t1);
        t1 = fmaf(rz, w1rz.y, t1);

        float2 hv;
        hv.x = gelu_fast(t0);
        hv.y = gelu_fast(t1);
        h1w2[k * 32 + lane] = hv;
    }
    __syncwarp();

    // ---- Phase B2: layer-2 + gelu + accumulate (ascending-distance order) ----
    float b2v = b2s[lane];
    float agg = 0.0f;
    #pragma unroll 2
    for (int k = 0; k < KNN; ++k) {
        const float* hk = &h1s[w][k][0];
        float acc = 0.0f;
        #pragma unroll
        for (int i2 = 0; i2 < 64; i2 += 4) {
            float4 h = *reinterpret_cast<const float4*>(hk + i2);
            acc = fmaf(h.x, w2r[i2 + 0], acc);
            acc = fmaf(h.y, w2r[i2 + 1], acc);
            acc = fmaf(h.z, w2r[i2 + 2], acc);
            acc = fmaf(h.w, w2r[i2 + 3], acc);
        }
        agg = __fadd_rn(agg, gelu_fast(__fadd_rn(acc, b2v)));
    }

    // ---- mean over K, out transform ----
    aggs[w][lane] = __fmul_rn(agg, 0.0625f);
    __syncwarp();
    float acc = 0.0f;
    #pragma unroll
    for (int i2 = 0; i2 < 32; ++i2)
        acc = fmaf(aggs[w][i2], W3s[i2 * 32 + lane], acc);
    out[(size_t)p * 32 + lane] = gelu_fast(__fadd_rn(acc, b3s[lane]));
}

// ---------------------------------------------------------------------------
// launch
// ---------------------------------------------------------------------------
extern "C" void kernel_launch(void* const* d_in, const int* in_sizes, int n_in,
                              void* d_out, int out_size) {
    const float* gv = (const float*)d_in[0];
    const float* gf = (const float*)d_in[1];
    const float* pv = (const float*)d_in[2];
    const float* pf = (const float*)d_in[3];
    const float* W1 = (const float*)d_in[4];
    const float* b1 = (const float*)d_in[5];
    const float* W2 = (const float*)d_in[6];
    const float* b2 = (const float*)d_in[7];
    const float* W3 = (const float*)d_in[8];
    const float* b3 = (const float*)d_in[9];
    float* out = (float*)d_out;

    gpre_kernel<<<NGRID / 32, 256>>>(gf, W1);
    fused_kernel<<<NPTS / 8, 256>>>(gv, pv, pf, W1, b1, W2, b2, W3, b3, out);
}

// round 4
// speedup vs baseline: 1.3018x; 1.0119x over previous
#include <cuda_runtime.h>
#include <math.h>

// ---------------------------------------------------------------------------
// GridFeatureToPointGraphConv — R4: f32x2 packed math (FFMA2) in all hot loops,
// packed-pair W2/W3 tables, trimmed bitonic cleanup. Per-component rounding
// identical to R3; only dot-product even/odd reassociation (~1e-7).
// ---------------------------------------------------------------------------

#define RES 48
#define NGRID (RES*RES*RES)      // 110592
#define NPTS 65536
#define HID 64
#define KNN 16

typedef unsigned long long u64;

__device__ float g_Gpre[NGRID * HID];   // 28.3 MB scratch (fits in L2)
__device__ u64   g_W2p[32 * 32];        // {W2[2i][o], W2[2i+1][o]} pairs
__device__ u64   g_W3p[16 * 32];        // {W3[2i][o], W3[2i+1][o]} pairs

// ---- f32x2 helpers -------------------------------------------------------
__device__ __forceinline__ u64 pack2(float lo, float hi) {
    u64 r; asm("mov.b64 %0, {%1,%2};" : "=l"(r) : "f"(lo), "f"(hi)); return r;
}
__device__ __forceinline__ void unpack2(u64 v, float& lo, float& hi) {
    asm("mov.b64 {%0,%1}, %2;" : "=f"(lo), "=f"(hi) : "l"(v));
}
__device__ __forceinline__ u64 fma2(u64 a, u64 b, u64 c) {
    u64 d; asm("fma.rn.f32x2 %0, %1, %2, %3;" : "=l"(d) : "l"(a), "l"(b), "l"(c)); return d;
}
__device__ __forceinline__ u64 mul2(u64 a, u64 b) {
    u64 d; asm("mul.rn.f32x2 %0, %1, %2;" : "=l"(d) : "l"(a), "l"(b)); return d;
}
__device__ __forceinline__ u64 add2(u64 a, u64 b) {
    u64 d; asm("add.rn.f32x2 %0, %1, %2;" : "=l"(d) : "l"(a), "l"(b)); return d;
}
__device__ __forceinline__ float ex2f(float x) {
    float r; asm("ex2.approx.f32 %0, %1;" : "=f"(r) : "f"(x)); return r;
}
__device__ __forceinline__ float rcpf(float x) {
    float r; asm("rcp.approx.f32 %0, %1;" : "=f"(r) : "f"(x)); return r;
}

// gelu_tanh(x) == x / (1 + e^{-p}), p = 1.5957691216x + 0.07135481681x^3
__device__ __forceinline__ float gelu_fast(float x) {
    float u = x * x;
    float w = __fmaf_rn(0.07135481681f, u, 1.5957691216f);
    float p = x * w;
    float e = __expf(-p);
    return __fdividef(x, 1.0f + e);
}

// paired gelu: componentwise identical rounding to gelu_fast
__device__ __forceinline__ u64 gelu2(u64 x, u64 C0, u64 C1, u64 NL2E, u64 ONE2) {
    u64 u = mul2(x, x);
    u64 w = fma2(u, C0, C1);
    u64 p = mul2(x, w);
    u64 m = mul2(p, NL2E);              // (-log2e)*p  == __expf(-p) argument
    float m0, m1; unpack2(m, m0, m1);
    u64 e = pack2(ex2f(m0), ex2f(m1));
    u64 den = add2(ONE2, e);
    float d0, d1; unpack2(den, d0, d1);
    u64 r = pack2(rcpf(d0), rcpf(d1));
    return mul2(x, r);
}

// ---------------------------------------------------------------------------
// Kernel 1: Gpre[g][i] = sum_c grid_features[g][c] * W1[c][i]   (rows 0..31)
//           + pack W2/W3 pair tables (block 0)
// ---------------------------------------------------------------------------
__global__ __launch_bounds__(256) void gpre_kernel(const float* __restrict__ gf,
                                                   const float* __restrict__ W1,
                                                   const float* __restrict__ W2,
                                                   const float* __restrict__ W3) {
    __shared__ float W1s[32 * 64];
    __shared__ float gfs[4 * 32];
    int tid = threadIdx.x;
    for (int t = tid; t < 32 * 64; t += 256) W1s[t] = W1[t];

    if (blockIdx.x == 0) {
        for (int j = tid; j < 32 * 32; j += 256) {
            int i = j >> 5, o = j & 31;
            g_W2p[j] = pack2(W2[(2 * i) * 32 + o], W2[(2 * i + 1) * 32 + o]);
        }
        for (int j = tid; j < 16 * 32; j += 256) {
            int i = j >> 5, o = j & 31;
            g_W3p[j] = pack2(W3[(2 * i) * 32 + o], W3[(2 * i + 1) * 32 + o]);
        }
    }

    int i = tid & 63;
    int v = tid >> 6;
    int base = blockIdx.x * 32;

    for (int it = 0; it < 8; ++it) {
        int g = base + it * 4;
        __syncthreads();
        if (tid < 128) gfs[tid] = gf[(size_t)g * 32 + tid];
        __syncthreads();
        float acc = 0.0f;
        #pragma unroll
        for (int c = 0; c < 32; ++c)
            acc = fmaf(gfs[v * 32 + c], W1s[c * 64 + i], acc);
        g_Gpre[(size_t)g * 64 + (size_t)tid] = acc;
    }
}

// ---------------------------------------------------------------------------
// Candidate distance, matching reference expansion: qq - 2*(q.p) + pp
// ---------------------------------------------------------------------------
__device__ __forceinline__ float cand_dist(int t, int ix0, int iy0, int iz0,
                                           const float* __restrict__ lins,
                                           float qx, float qy, float qz, float qq) {
    int a = t >> 4, b = (t >> 2) & 3, c = t & 3;
    float px = lins[ix0 + a], py = lins[iy0 + b], pz = lins[iz0 + c];
    float pp = __fadd_rn(__fadd_rn(__fmul_rn(px, px), __fmul_rn(py, py)), __fmul_rn(pz, pz));
    float dot = __fmaf_rn(qz, pz, __fmaf_rn(qy, py, __fmul_rn(qx, px)));
    return __fadd_rn(__fsub_rn(qq, __fadd_rn(dot, dot)), pp);
}

__device__ __forceinline__ unsigned int fmap(float d) {
    unsigned int b = __float_as_uint(d);
    return (b & 0x80000000u) ? ~b : (b | 0x80000000u);
}

__device__ __forceinline__ u64 bitonic_ce(u64 key, int j, bool up, int lane) {
    u64 pk = __shfl_xor_sync(0xffffffffu, key, j);
    bool lower = ((lane & j) == 0);
    u64 mn = (key < pk) ? key : pk;
    u64 mx = (key < pk) ? pk : key;
    return ((lower == up)) ? mn : mx;
}

// ---------------------------------------------------------------------------
// Kernel 2: fused KNN + edge MLP + mean + out MLP. One warp per point.
// ---------------------------------------------------------------------------
__global__ __launch_bounds__(256, 2) void fused_kernel(
    const float* __restrict__ gv,
    const float* __restrict__ pv,
    const float* __restrict__ pf,
    const float* __restrict__ W1,
    const float* __restrict__ b1,
    const float* __restrict__ b2,
    const float* __restrict__ b3,
    float* __restrict__ out)
{
    __shared__ float lins[RES];
    __shared__ __align__(16) float W1s[35 * 64];     // W1 rows 32..66 (self + rel)
    __shared__ float b1s[64];
    __shared__ float b2s[32];
    __shared__ float b3s[32];
    __shared__ __align__(16) float h1s[8][16][64];   // per-warp, per-edge hidden
    __shared__ __align__(16) float aggs[8][32];

    int tid = threadIdx.x;
    for (int t = tid; t < 35 * 64; t += 256) W1s[t] = W1[32 * 64 + t];
    if (tid < 64) b1s[tid] = b1[tid];
    if (tid >= 64 && tid < 96)  b2s[tid - 64] = b2[tid - 64];
    if (tid >= 96 && tid < 128) b3s[tid - 96] = b3[tid - 96];
    if (tid >= 128 && tid < 128 + RES)
        lins[tid - 128] = __fmul_rn(gv[3 * (tid - 128) + 2], 24.0f);
    __syncthreads();

    const int w = tid >> 5;
    const int lane = tid & 31;
    const int p = blockIdx.x * 8 + w;

    const u64 C0   = pack2(0.07135481681f, 0.07135481681f);
    const u64 C1   = pack2(1.5957691216f, 1.5957691216f);
    const u64 NL2E = pack2(-1.442695041f, -1.442695041f);
    const u64 ONE2 = pack2(1.0f, 1.0f);

    // W2 pair-column for this lane (output channel = lane)
    u64 w2p[32];
    #pragma unroll
    for (int i2 = 0; i2 < 32; ++i2) w2p[i2] = __ldg(&g_W2p[i2 * 32 + lane]);

    // point coords (scaled)
    float qxu = __ldg(&pv[p * 3 + 0]);
    float qyu = __ldg(&pv[p * 3 + 1]);
    float qzu = __ldg(&pv[p * 3 + 2]);
    float qx = __fmul_rn(qxu, 24.0f);
    float qy = __fmul_rn(qyu, 24.0f);
    float qz = __fmul_rn(qzu, 24.0f);
    float qq = __fadd_rn(__fadd_rn(__fmul_rn(qx, qx), __fmul_rn(qy, qy)), __fmul_rn(qz, qz));

    // per-point layer-1 partial (channels 2*lane, 2*lane+1), packed
    const u64* W1su = reinterpret_cast<const u64*>(W1s);
    u64 pre2 = pack2(b1s[lane * 2], b1s[lane * 2 + 1]);
    {
        const float4* pf4 = reinterpret_cast<const float4*>(pf + (size_t)p * 32);
        #pragma unroll
        for (int c4 = 0; c4 < 8; ++c4) {
            float4 f = __ldg(&pf4[c4]);
            pre2 = fma2(pack2(f.x, f.x), W1su[(c4 * 4 + 0) * 32 + lane], pre2);
            pre2 = fma2(pack2(f.y, f.y), W1su[(c4 * 4 + 1) * 32 + lane], pre2);
            pre2 = fma2(pack2(f.z, f.z), W1su[(c4 * 4 + 2) * 32 + lane], pre2);
            pre2 = fma2(pack2(f.w, f.w), W1su[(c4 * 4 + 3) * 32 + lane], pre2);
        }
    }
    u64 w1rx2 = W1su[32 * 32 + lane];
    u64 w1ry2 = W1su[33 * 32 + lane];
    u64 w1rz2 = W1su[34 * 32 + lane];

    // ---- Phase A: selection via bitonic sort of 64 (d, t) keys ----
    int ix0 = min(max((int)floorf((qxu + 1.0f) * 23.5f) - 1, 0), RES - 4);
    int iy0 = min(max((int)floorf((qyu + 1.0f) * 23.5f) - 1, 0), RES - 4);
    int iz0 = min(max((int)floorf((qzu + 1.0f) * 23.5f) - 1, 0), RES - 4);

    float dA = cand_dist(lane,      ix0, iy0, iz0, lins, qx, qy, qz, qq);
    float dB = cand_dist(lane + 32, ix0, iy0, iz0, lins, qx, qy, qz, qq);
    u64 key0 = ((u64)fmap(dA) << 32) | (unsigned int)lane;
    u64 key1 = ((u64)fmap(dB) << 32) | (unsigned int)(lane + 32);

    #pragma unroll
    for (int ks = 2; ks <= 32; ks <<= 1) {
        bool up0 = ((lane & ks) == 0);
        bool up1 = (((lane + 32) & ks) == 0);
        #pragma unroll
        for (int j = ks >> 1; j > 0; j >>= 1) {
            key0 = bitonic_ce(key0, j, up0, lane);
            key1 = bitonic_ce(key1, j, up1, lane);
        }
    }
    // final stage: keep only the min half (top-32), clean 5 levels on key0
    {
        key0 = (key0 < key1) ? key0 : key1;
        #pragma unroll
        for (int j = 16; j > 0; j >>= 1)
            key0 = bitonic_ce(key0, j, true, lane);
    }
    int myt = (int)((unsigned int)key0 & 63u);   // lane k (<16) holds rank-k neighbor

    // ---- Phase B1: edge layer-1 for all 16 edges (packed) ----
    const u64* Gpreu = reinterpret_cast<const u64*>(g_Gpre);
    u64* h1u = reinterpret_cast<u64*>(&h1s[w][0][0]);
    const int gbase = ix0 * (RES * RES) + iy0 * RES + iz0;
    #pragma unroll 4
    for (int k = 0; k < KNN; ++k) {
        int t = __shfl_sync(0xffffffffu, myt, k);
        int a = t >> 4, b = (t >> 2) & 3, c = t & 3;
        int gm = gbase + a * (RES * RES) + b * RES + c;
        float rx = __fsub_rn(lins[ix0 + a], qx);
        float ry = __fsub_rn(lins[iy0 + b], qy);
        float rz = __fsub_rn(lins[iz0 + c], qz);

        u64 gp = __ldg(&Gpreu[(size_t)gm * 32 + lane]);
        u64 t2 = add2(pre2, gp);
        t2 = fma2(pack2(rx, rx), w1rx2, t2);
        t2 = fma2(pack2(ry, ry), w1ry2, t2);
        t2 = fma2(pack2(rz, rz), w1rz2, t2);
        h1u[k * 32 + lane] = gelu2(t2, C0, C1, NL2E, ONE2);
    }
    __syncwarp();

    // ---- Phase B2: layer-2 (packed dot) + gelu + accumulate ----
    float b2v = b2s[lane];
    float agg = 0.0f;
    #pragma unroll 2
    for (int k = 0; k < KNN; ++k) {
        const ulonglong2* hk2 = reinterpret_cast<const ulonglong2*>(&h1s[w][k][0]);
        u64 acc2 = pack2(0.0f, 0.0f);
        #pragma unroll
        for (int i2 = 0; i2 < 16; ++i2) {
            ulonglong2 hp = hk2[i2];
            acc2 = fma2(hp.x, w2p[2 * i2 + 0], acc2);
            acc2 = fma2(hp.y, w2p[2 * i2 + 1], acc2);
        }
        float a0, a1; unpack2(acc2, a0, a1);
        float acc = __fadd_rn(__fadd_rn(a0, a1), b2v);
        agg = __fadd_rn(agg, gelu_fast(acc));
    }

    // ---- mean over K, out transform (packed) ----
    aggs[w][lane] = __fmul_rn(agg, 0.0625f);
    __syncwarp();
    const u64* ag2 = reinterpret_cast<const u64*>(&aggs[w][0]);
    u64 acc2 = pack2(0.0f, 0.0f);
    #pragma unroll
    for (int i2 = 0; i2 < 16; ++i2)
        acc2 = fma2(ag2[i2], __ldg(&g_W3p[i2 * 32 + lane]), acc2);
    float a0, a1; unpack2(acc2, a0, a1);
    float acc = __fadd_rn(__fadd_rn(a0, a1), b3s[lane]);
    out[(size_t)p * 32 + lane] = gelu_fast(acc);
}

// ---------------------------------------------------------------------------
// launch
// ---------------------------------------------------------------------------
extern "C" void kernel_launch(void* const* d_in, const int* in_sizes, int n_in,
                              void* d_out, int out_size) {
    const float* gv = (const float*)d_in[0];
    const float* gf = (const float*)d_in[1];
    const float* pv = (const float*)d_in[2];
    const float* pf = (const float*)d_in[3];
    const float* W1 = (const float*)d_in[4];
    const float* b1 = (const float*)d_in[5];
    const float* W2 = (const float*)d_in[6];
    const float* b2 = (const float*)d_in[7];
    const float* W3 = (const float*)d_in[8];
    const float* b3 = (const float*)d_in[9];
    float* out = (float*)d_out;

    gpre_kernel<<<NGRID / 32, 256>>>(gf, W1, W2, W3);
    fused_kernel<<<NPTS / 8, 256>>>(gv, pv, pf, W1, b1, b2, b3, out);
}